// round 16
// baseline (speedup 1.0000x reference)
#include <cuda_runtime.h>
#include <cuda_fp16.h>
#include <math.h>
#include <stdint.h>

#define SS 4096
#define DD 768
#define HH 12
#define DHH 64
#define NBB 64
#define BSS 64
#define RRR 3
#define FFF 3072
#define CCC 8
#define NQKV 2304
#define MTAIL 128
#define ROW0 (SS - MTAIL)
#define PSZ ((size_t)SS * DD)      // partial-buffer stride

// ---------------- scratch (device globals; no allocation allowed) -----------
__device__ __align__(16) float g_h  [SS*DD];
__device__ __align__(16) float g_ap [4*SS*DD];  // split-K partials (up to 4)
__device__ __align__(16) __half g_ah[SS*FFF];   // activation hi
__device__ __align__(16) __half g_bh[SS*FFF];   // qkv hi / ffn-hidden hi
// per-layer fp16 weights (hi only)
__device__ __align__(16) __half g_wqkv[2][3*DD*DD];
__device__ __align__(16) __half g_wo  [2][DD*DD];
__device__ __align__(16) __half g_w1  [2][DD*FFF];
__device__ __align__(16) __half g_w2  [2][FFF*DD];
__device__ __align__(16) float  g_bias3[2][NQKV];
// edge-attention partials: 24 (h,e) x 8 chunks x 64 q x 64 d
__device__ __align__(16) float g_pO[24*8*64*64];
__device__ __align__(16) float g_pm[24*8*64];
__device__ __align__(16) float g_pl[24*8*64];

// ---------------- PTX helpers ------------------------------------------------
__device__ __forceinline__ uint32_t smem_addr(const void* p) {
    uint32_t a;
    asm("{ .reg .u64 t; cvta.to.shared.u64 t, %1; cvt.u32.u64 %0, t; }" : "=r"(a) : "l"(p));
    return a;
}
__device__ __forceinline__ void ldsm_x4(uint32_t addr, uint32_t* r) {
    asm volatile("ldmatrix.sync.aligned.m8n8.x4.shared.b16 {%0,%1,%2,%3}, [%4];"
        : "=r"(r[0]), "=r"(r[1]), "=r"(r[2]), "=r"(r[3]) : "r"(addr));
}
__device__ __forceinline__ void ldsm_x4_t(uint32_t addr, uint32_t* r) {
    asm volatile("ldmatrix.sync.aligned.m8n8.x4.trans.shared.b16 {%0,%1,%2,%3}, [%4];"
        : "=r"(r[0]), "=r"(r[1]), "=r"(r[2]), "=r"(r[3]) : "r"(addr));
}
__device__ __forceinline__ void mma_f16(float* c, const uint32_t* a, const uint32_t* b) {
    asm volatile("mma.sync.aligned.m16n8k16.row.col.f32.f16.f16.f32 "
        "{%0,%1,%2,%3}, {%4,%5,%6,%7}, {%8,%9}, {%0,%1,%2,%3};"
        : "+f"(c[0]), "+f"(c[1]), "+f"(c[2]), "+f"(c[3])
        : "r"(a[0]), "r"(a[1]), "r"(a[2]), "r"(a[3]), "r"(b[0]), "r"(b[1]));
}
__device__ __forceinline__ void mma4(float* c, const uint32_t* a, uint32_t b0, uint32_t b1) {
    uint32_t b[2] = {b0, b1};
    mma_f16(c, a, b);
}
#define CP_ASYNC(dst, src) asm volatile("cp.async.cg.shared.global [%0], [%1], 16;" :: "r"(dst), "l"(src))
#define CP_COMMIT()        asm volatile("cp.async.commit_group;")
#define CP_WAIT(n)         asm volatile("cp.async.wait_group %0;" :: "n"(n))

__device__ __forceinline__ uint32_t pack_h2(__half a, __half b) {
    __half2 t; t.x = a; t.y = b;
    return *(uint32_t*)&t;
}
__device__ __forceinline__ float tanh_fast(float x) {
    float y;
    asm("tanh.approx.f32 %0, %1;" : "=f"(y) : "f"(x));
    return y;
}

// ---------------- fp16 1-pass GEMM via mma.sync -------------------------------
// C = Ah * Bh^T + bias (fp32 accum). 2 tiles/stage, NS-stage cp.async pipeline.
// Split-K via blockIdx.z: partial z writes C + z*psz; bias only on z=0.
// ldo: output row stride. modes: 0 fp32 out, 4 gelu + fp16 hi, 5 fp16 hi
#define GEMM_SMEM 98304

template<int NS>
__global__ void __launch_bounds__(256, 2)
gemm_mma(const __half* __restrict__ Ah, const __half* __restrict__ Bh,
         const float* __restrict__ bias, float* __restrict__ C, size_t psz,
         __half* __restrict__ Oh,
         int M, int N, int K, int ldo, int mode)
{
    constexpr int STAGE = 2 * 16384;
    extern __shared__ __align__(128) char smem[];
    uint32_t sb = smem_addr(smem);
    int tid = threadIdx.x, lane = tid & 31, wid = tid >> 5;
    int wm = wid & 1, wn = wid >> 1;
    int n0 = blockIdx.x * 128, m0 = blockIdx.y * 128;
    int kz = blockIdx.z, nz = gridDim.z;
    const int KT = (K >> 6) / nz;
    const int kbase = kz * KT;
    float* Cout = C + (size_t)kz * psz;
    float bsc = (kz == 0) ? 1.f : 0.f;

    const __half* srcA = Ah + (size_t)m0 * K;
    const __half* srcB = Bh + (size_t)n0 * K;

    float acc[4][4][4];
#pragma unroll
    for (int i = 0; i < 4; i++)
#pragma unroll
        for (int j = 0; j < 4; j++)
#pragma unroll
            for (int u = 0; u < 4; u++) acc[i][j][u] = 0.f;

    auto load_stage = [&](int S, int ktIdx) {
        uint32_t sbase = sb + S * STAGE;
        int ko = (kbase + ktIdx) * 64;
#pragma unroll
        for (int t = 0; t < 2; t++) {
            const __half* sp = t ? srcB : srcA;
#pragma unroll
            for (int i = 0; i < 4; i++) {
                int id = tid + i * 256;
                int row = id >> 3, c = id & 7;
                const __half* src = sp + (size_t)row * K + ko + c * 8;
                uint32_t dst = sbase + t * 16384 + row * 128 + ((c ^ (row & 7)) << 4);
                CP_ASYNC(dst, src);
            }
        }
        CP_COMMIT();
    };

#pragma unroll
    for (int s = 0; s < NS - 1; s++)
        if (s < KT) load_stage(s, s);

    for (int kt = 0; kt < KT; kt++) {
        if (kt + NS - 1 < KT) { load_stage((kt + NS - 1) % NS, kt + NS - 1); CP_WAIT(NS - 1); }
        else                  { CP_WAIT(0); }
        __syncthreads();
        uint32_t st = sb + (kt % NS) * STAGE;
#pragma unroll
        for (int ks = 0; ks < 4; ks++) {
            uint32_t ahf[4][4], bhf[2][4];
#pragma unroll
            for (int mt = 0; mt < 4; mt++) {
                int row = wm * 64 + mt * 16 + (lane & 15);
                int kc = ks * 2 + (lane >> 4);
                uint32_t off = row * 128 + ((kc ^ (row & 7)) << 4);
                ldsm_x4(st + off, ahf[mt]);
            }
#pragma unroll
            for (int np = 0; np < 2; np++) {
                int row = wn * 32 + np * 16 + ((lane & 7) | ((lane & 16) >> 1));
                int kc = ks * 2 + ((lane >> 3) & 1);
                uint32_t off = row * 128 + ((kc ^ (row & 7)) << 4);
                ldsm_x4(st + 16384 + off, bhf[np]);
            }
#pragma unroll
            for (int mt = 0; mt < 4; mt++)
#pragma unroll
                for (int nt = 0; nt < 4; nt++)
                    mma_f16(acc[mt][nt], ahf[mt], &bhf[nt >> 1][(nt & 1) * 2]);
        }
        __syncthreads();
    }

#pragma unroll
    for (int mt = 0; mt < 4; mt++) {
        int mbase = m0 + wm * 64 + mt * 16 + (lane >> 2);
#pragma unroll
        for (int nt = 0; nt < 4; nt++) {
            int n = n0 + wn * 32 + nt * 8 + (lane & 3) * 2;
            float b0 = bias[n] * bsc, b1 = bias[n + 1] * bsc;
#pragma unroll
            for (int half = 0; half < 2; half++) {
                int m = mbase + half * 8;
                float v0 = acc[mt][nt][half * 2 + 0] + b0;
                float v1 = acc[mt][nt][half * 2 + 1] + b1;
                if (mode == 4) {
                    float u0 = 0.7978845608028654f * (v0 + 0.044715f * v0 * v0 * v0);
                    v0 = 0.5f * v0 * (1.f + tanh_fast(u0));
                    float u1 = 0.7978845608028654f * (v1 + 0.044715f * v1 * v1 * v1);
                    v1 = 0.5f * v1 * (1.f + tanh_fast(u1));
                }
                if (mode >= 4) {
                    *(uint32_t*)(Oh + (size_t)m * ldo + n) = pack_h2(__float2half_rn(v0), __float2half_rn(v1));
                } else {
                    float2 o; o.x = v0; o.y = v1;
                    *(float2*)(Cout + (size_t)m * ldo + n) = o;
                }
            }
        }
    }
}

// ---------------- W[K,N] fp32 -> Wt[N,K] fp16 hi ------------------------------
__global__ __launch_bounds__(256) void conv_wt(const float* __restrict__ W,
    __half* __restrict__ th, int K, int N)
{
    __shared__ float tile[32][33];
    int k0 = blockIdx.y * 32, n0 = blockIdx.x * 32;
    int tx = threadIdx.x & 31, ty = threadIdx.x >> 5;
#pragma unroll
    for (int r = ty; r < 32; r += 8)
        tile[r][tx] = W[(size_t)(k0 + r) * N + n0 + tx];
    __syncthreads();
#pragma unroll
    for (int r = ty; r < 32; r += 8) {
        float v = tile[tx][r];
        th[(size_t)(n0 + r) * K + k0 + tx] = __float2half_rn(v);
    }
}

__global__ __launch_bounds__(256) void concat3(const float* __restrict__ a,
    const float* __restrict__ b, const float* __restrict__ c, float* __restrict__ o)
{
    int i = blockIdx.x * 256 + threadIdx.x;
    if (i < DD) { o[i] = a[i]; o[DD + i] = b[i]; o[2 * DD + i] = c[i]; }
}

// ---------------- reductions -------------------------------------------------
__device__ __forceinline__ void block_reduce2(float &s1v, float &s2v) {
    __shared__ float sa[8], sb2[8];
    int lane = threadIdx.x & 31, w = threadIdx.x >> 5;
#pragma unroll
    for (int off = 16; off; off >>= 1) {
        s1v += __shfl_xor_sync(0xffffffffu, s1v, off);
        s2v += __shfl_xor_sync(0xffffffffu, s2v, off);
    }
    if (lane == 0) { sa[w] = s1v; sb2[w] = s2v; }
    __syncthreads();
    if (w == 0) {
        s1v = (lane < 8) ? sa[lane] : 0.f;
        s2v = (lane < 8) ? sb2[lane] : 0.f;
#pragma unroll
        for (int off = 4; off; off >>= 1) {
            s1v += __shfl_xor_sync(0xffffffffu, s1v, off);
            s2v += __shfl_xor_sync(0xffffffffu, s2v, off);
        }
        if (lane == 0) { sa[0] = s1v; sb2[0] = s2v; }
    }
    __syncthreads();
    s1v = sa[0]; s2v = sb2[0];
}

// ---------------- embedding + LN (hi out) -------------------------------------
__global__ __launch_bounds__(256) void embed_ln_split(
    const int* __restrict__ ids, const float* __restrict__ we,
    const float* __restrict__ pe, const float* __restrict__ w,
    const float* __restrict__ b, float* __restrict__ out,
    __half* __restrict__ oh)
{
    int row = blockIdx.x;
    int id = ids[row];
    float x[3], sum = 0.f, sq = 0.f;
#pragma unroll
    for (int r = 0; r < 3; r++) {
        int i = threadIdx.x + r * 256;
        x[r] = we[(long long)id * DD + i] + pe[row * DD + i];
        sum += x[r]; sq += x[r] * x[r];
    }
    block_reduce2(sum, sq);
    float mean = sum * (1.f / DD);
    float var  = sq * (1.f / DD) - mean * mean;
    float inv  = rsqrtf(var + 1e-12f);
#pragma unroll
    for (int r = 0; r < 3; r++) {
        int i = threadIdx.x + r * 256;
        float y = (x[r] - mean) * inv * w[i] + b[i];
        out[row * DD + i] = y;
        oh[row * DD + i] = __float2half_rn(y);
    }
}

// -------- residual (h + sum of nz split-K partials) + LN (hi out) --------------
__global__ __launch_bounds__(256) void add_lnN(
    float* __restrict__ h, const float* __restrict__ ap, size_t psz, int nz,
    const float* __restrict__ w, const float* __restrict__ b,
    __half* __restrict__ oh)
{
    int row = blockIdx.x;
    float x[3], sum = 0.f, sq = 0.f;
#pragma unroll
    for (int r = 0; r < 3; r++) {
        int i = threadIdx.x + r * 256;
        float v = h[row * DD + i];
        for (int z = 0; z < nz; z++)
            v += ap[(size_t)z * psz + row * DD + i];
        x[r] = v;
        sum += v; sq += v * v;
    }
    block_reduce2(sum, sq);
    float mean = sum * (1.f / DD);
    float var  = sq * (1.f / DD) - mean * mean;
    float inv  = rsqrtf(var + 1e-12f);
#pragma unroll
    for (int r = 0; r < 3; r++) {
        int i = threadIdx.x + r * 256;
        float y = (x[r] - mean) * inv * w[i] + b[i];
        h[row * DD + i] = y;
        oh[row * DD + i] = __float2half_rn(y);
    }
}

// ---------------- MMA flash attention (fp16, 1-pass) ---------------------------
#define AS_Q 0
#define AS_KV 8192
#define KV_STAGE 16384
#define ATTN_SMEM (8192 + 2 * KV_STAGE)

__global__ void __launch_bounds__(128)
attn_mma_kernel(const __half* __restrict__ sh, const int* __restrict__ rnd,
                __half* __restrict__ th,
                float* __restrict__ pO, float* __restrict__ pm, float* __restrict__ pl,
                int ybase)
{
    extern __shared__ __align__(128) char smem[];
    uint32_t sb = smem_addr(smem);
    int h = blockIdx.x, y = blockIdx.y + ybase;
    int tid = threadIdx.x, lane = tid & 31, w = tid >> 5;

    int qb, e = 0, z = 0;
    bool edge;
    if (y < 62) { qb = y + 1; edge = false; }
    else        { int t = y - 62; e = t >> 3; z = t & 7; qb = e ? (NBB - 1) : 0; edge = true; }

    int blks[8];
    if (edge) {
#pragma unroll
        for (int i = 0; i < 8; i++) blks[i] = z * 8 + i;
    } else {
        blks[0] = 0; blks[1] = NBB - 1; blks[2] = qb - 1; blks[3] = qb; blks[4] = qb + 1;
        const int* rp = rnd + (h * NBB + qb) * RRR;
        blks[5] = rp[0]; blks[6] = rp[1]; blks[7] = rp[2];
    }

    // ---- Q tile (hi) ----
    {
        int colq = h * DHH;
#pragma unroll
        for (int i = 0; i < 4; i++) {
            int idx = tid + i * 128;
            int row = idx >> 3, cu = idx & 7;
            const __half* src = sh + (size_t)(qb * BSS + row) * NQKV + colq + cu * 8;
            uint32_t dst = sb + AS_Q + row * 128 + ((cu ^ (row & 7)) << 4);
            CP_ASYNC(dst, src);
        }
    }
#define LOAD_KV(STG, KB) do {                                                   \
    uint32_t base_ = sb + AS_KV + (STG) * KV_STAGE;                             \
    _Pragma("unroll")                                                           \
    for (int i_ = 0; i_ < 8; i_++) {                                            \
        int idx_ = tid + i_ * 128;                                              \
        int t_ = idx_ >> 9, rem_ = idx_ & 511;                                  \
        int row_ = rem_ >> 3, cu_ = rem_ & 7;                                   \
        int col_ = (t_ + 1) * DD + h * DHH + cu_ * 8;                           \
        const __half* src_ = sh + (size_t)((KB) * BSS + row_) * NQKV + col_;    \
        uint32_t dst_ = base_ + t_ * 8192 + row_ * 128 + ((cu_ ^ (row_ & 7)) << 4); \
        CP_ASYNC(dst_, src_);                                                   \
    }                                                                           \
} while (0)

    LOAD_KV(0, blks[0]);
    CP_COMMIT();
    CP_WAIT(0);
    __syncthreads();

    uint32_t qfh[4][4];
#pragma unroll
    for (int ds = 0; ds < 4; ds++) {
        int row = w * 16 + (lane & 15);
        int cu = ds * 2 + (lane >> 4);
        uint32_t off = row * 128 + ((cu ^ (row & 7)) << 4);
        ldsm_x4(sb + AS_Q + off, qfh[ds]);
    }

    float o[8][4];
    float m[2] = {-1e30f, -1e30f}, l[2] = {0.f, 0.f};
#pragma unroll
    for (int j = 0; j < 8; j++)
#pragma unroll
        for (int u = 0; u < 4; u++) o[j][u] = 0.f;

    const float sc = 0.125f;

    for (int b = 0; b < 8; b++) {
        if (b + 1 < 8) { LOAD_KV((b + 1) & 1, blks[b + 1]); CP_COMMIT(); }
        uint32_t st = sb + AS_KV + (b & 1) * KV_STAGE;

        float s[8][4];
#pragma unroll
        for (int j = 0; j < 8; j++)
#pragma unroll
            for (int u = 0; u < 4; u++) s[j][u] = 0.f;
#pragma unroll
        for (int kb = 0; kb < 4; kb++) {
#pragma unroll
            for (int ds = 0; ds < 4; ds++) {
                int row = kb * 16 + (lane & 15);
                int cu = ds * 2 + (lane >> 4);
                uint32_t off = st + row * 128 + ((cu ^ (row & 7)) << 4);
                uint32_t kh4[4];
                ldsm_x4(off, kh4);
                mma4(s[2 * kb],     qfh[ds], kh4[0], kh4[2]);
                mma4(s[2 * kb + 1], qfh[ds], kh4[1], kh4[3]);
            }
        }

#pragma unroll
        for (int hf = 0; hf < 2; hf++) {
            float rm = -1e30f;
#pragma unroll
            for (int j = 0; j < 8; j++)
                rm = fmaxf(rm, fmaxf(s[j][hf * 2], s[j][hf * 2 + 1]));
            rm *= sc;
            rm = fmaxf(rm, __shfl_xor_sync(0xffffffffu, rm, 1));
            rm = fmaxf(rm, __shfl_xor_sync(0xffffffffu, rm, 2));
            float mn = fmaxf(m[hf], rm);
            float corr = __expf(m[hf] - mn);
            m[hf] = mn;
            float rs = 0.f;
#pragma unroll
            for (int j = 0; j < 8; j++) {
                s[j][hf * 2]     = __expf(s[j][hf * 2]     * sc - mn);
                s[j][hf * 2 + 1] = __expf(s[j][hf * 2 + 1] * sc - mn);
                rs += s[j][hf * 2] + s[j][hf * 2 + 1];
            }
            rs += __shfl_xor_sync(0xffffffffu, rs, 1);
            rs += __shfl_xor_sync(0xffffffffu, rs, 2);
            l[hf] = l[hf] * corr + rs;
#pragma unroll
            for (int j = 0; j < 8; j++) {
                o[j][hf * 2]     *= corr;
                o[j][hf * 2 + 1] *= corr;
            }
        }

#pragma unroll
        for (int ks = 0; ks < 4; ks++) {
            uint32_t ph4[4];
            ph4[0] = pack_h2(__float2half_rn(s[2 * ks][0]),     __float2half_rn(s[2 * ks][1]));
            ph4[1] = pack_h2(__float2half_rn(s[2 * ks][2]),     __float2half_rn(s[2 * ks][3]));
            ph4[2] = pack_h2(__float2half_rn(s[2 * ks + 1][0]), __float2half_rn(s[2 * ks + 1][1]));
            ph4[3] = pack_h2(__float2half_rn(s[2 * ks + 1][2]), __float2half_rn(s[2 * ks + 1][3]));
#pragma unroll
            for (int dc = 0; dc < 4; dc++) {
                int row = ks * 16 + (lane & 15);
                int cu = dc * 2 + (lane >> 4);
                uint32_t off = st + 8192 + row * 128 + ((cu ^ (row & 7)) << 4);
                uint32_t vh4[4];
                ldsm_x4_t(off, vh4);
                mma4(o[2 * dc],     ph4, vh4[0], vh4[1]);
                mma4(o[2 * dc + 1], ph4, vh4[2], vh4[3]);
            }
        }

        if (b + 1 < 8) { CP_WAIT(0); __syncthreads(); }
    }

    int g = lane >> 2;
    if (!edge) {
#pragma unroll
        for (int hf = 0; hf < 2; hf++) {
            float inv = 1.f / l[hf];
            int row = qb * BSS + w * 16 + g + hf * 8;
#pragma unroll
            for (int j = 0; j < 8; j++) {
                int col = h * DHH + j * 8 + (lane & 3) * 2;
                *(uint32_t*)(th + (size_t)row * DD + col) =
                    pack_h2(__float2half_rn(o[j][hf * 2] * inv),
                            __float2half_rn(o[j][hf * 2 + 1] * inv));
            }
        }
    } else {
        int cb = (h * 2 + e) * 8 + z;
        float* po = pO + (size_t)cb * 64 * 64;
#pragma unroll
        for (int hf = 0; hf < 2; hf++) {
            int qr = w * 16 + g + hf * 8;
#pragma unroll
            for (int j = 0; j < 8; j++) {
                float2 val; val.x = o[j][hf * 2]; val.y = o[j][hf * 2 + 1];
                *(float2*)(po + qr * 64 + j * 8 + (lane & 3) * 2) = val;
            }
            if ((lane & 3) == 0) {
                pm[cb * 64 + qr] = m[hf];
                pl[cb * 64 + qr] = l[hf];
            }
        }
    }
}

// combine edge partials: grid (nhe, 64), 64 threads (d); he = x*hestep + heoff
__global__ void __launch_bounds__(64)
attn_combine(const float* __restrict__ pO, const float* __restrict__ pm,
             const float* __restrict__ pl, __half* __restrict__ th,
             int hestep, int heoff)
{
    int he = blockIdx.x * hestep + heoff, q = blockIdx.y, d = threadIdx.x;
    int h = he >> 1, e = he & 1;
    float mv[8], M = -1e30f;
#pragma unroll
    for (int z = 0; z < 8; z++) {
        mv[z] = pm[(he * 8 + z) * 64 + q];
        M = fmaxf(M, mv[z]);
    }
    float L = 0.f, O = 0.f;
#pragma unroll
    for (int z = 0; z < 8; z++) {
        float w = __expf(mv[z] - M);
        L += w * pl[(he * 8 + z) * 64 + q];
        O += w * pO[((size_t)(he * 8 + z) * 64 + q) * 64 + d];
    }
    float r = O / L;
    int row = (e ? (NBB - 1) : 0) * BSS + q;
    th[row * DD + h * DHH + d] = __float2half_rn(r);
}

// ---------------- classifier --------------------------------------------------
__global__ __launch_bounds__(256) void classifier_kernel(
    const float* __restrict__ h, const float* __restrict__ Wc,
    const float* __restrict__ bc, float* __restrict__ out)
{
    int warp = threadIdx.x >> 5, lane = threadIdx.x & 31;
    if (warp >= CCC) return;
    const float* hr = h + (long long)(SS - 1) * DD;
    float s = 0.f;
    for (int d = lane; d < DD; d += 32) s += hr[d] * Wc[d * CCC + warp];
#pragma unroll
    for (int off = 16; off; off >>= 1) s += __shfl_xor_sync(0xffffffffu, s, off);
    if (lane == 0) out[warp] = s + bc[warp];
}

// ---------------- launch ------------------------------------------------------
extern "C" void kernel_launch(void* const* d_in, const int* in_sizes, int n_in,
                              void* d_out, int out_size)
{
    (void)in_sizes; (void)n_in; (void)out_size;
    const int*   input_ids = (const int*)  d_in[0];
    const int*   rand_attn = (const int*)  d_in[1];
    const float* word_emb  = (const float*)d_in[2];
    const float* pos_emb   = (const float*)d_in[3];
    const float* eln_w     = (const float*)d_in[4];
    const float* eln_b     = (const float*)d_in[5];
    const float* Wq        = (const float*)d_in[6];
    const float* bq        = (const float*)d_in[7];
    const float* Wk        = (const float*)d_in[8];
    const float* bk        = (const float*)d_in[9];
    const float* Wv        = (const float*)d_in[10];
    const float* bv        = (const float*)d_in[11];
    const float* Wo        = (const float*)d_in[12];
    const float* bo        = (const float*)d_in[13];
    const float* ln1_w     = (const float*)d_in[14];
    const float* ln1_b     = (const float*)d_in[15];
    const float* W1        = (const float*)d_in[16];
    const float* b1        = (const float*)d_in[17];
    const float* W2        = (const float*)d_in[18];
    const float* b2        = (const float*)d_in[19];
    const float* ln2_w     = (const float*)d_in[20];
    const float* ln2_b     = (const float*)d_in[21];
    const float* Wc        = (const float*)d_in[22];
    const float* bc        = (const float*)d_in[23];
    float* out = (float*)d_out;

    cudaFuncSetAttribute(gemm_mma<3>, cudaFuncAttributeMaxDynamicSharedMemorySize, GEMM_SMEM);
    cudaFuncSetAttribute(attn_mma_kernel, cudaFuncAttributeMaxDynamicSharedMemorySize, ATTN_SMEM);

    float *h, *ap, *pO, *pm, *pl;
    __half *ah, *bh;
    __half *wqkv[2], *wo[2], *w1[2], *w2[2];
    float  *bias3[2];
    cudaGetSymbolAddress((void**)&h,  g_h);
    cudaGetSymbolAddress((void**)&ap, g_ap);
    cudaGetSymbolAddress((void**)&ah, g_ah);
    cudaGetSymbolAddress((void**)&bh, g_bh);
    cudaGetSymbolAddress((void**)&pO, g_pO);
    cudaGetSymbolAddress((void**)&pm, g_pm);
    cudaGetSymbolAddress((void**)&pl, g_pl);
    {
        __half *p0, *p1, *p2, *p3; float* p4;
        cudaGetSymbolAddress((void**)&p0, g_wqkv);
        cudaGetSymbolAddress((void**)&p1, g_wo);
        cudaGetSymbolAddress((void**)&p2, g_w1);
        cudaGetSymbolAddress((void**)&p3, g_w2);
        cudaGetSymbolAddress((void**)&p4, g_bias3);
        for (int l = 0; l < 2; l++) {
            wqkv[l] = p0 + (size_t)l * 3 * DD * DD;
            wo[l]   = p1 + (size_t)l * DD * DD;
            w1[l]   = p2 + (size_t)l * DD * FFF;
            w2[l]   = p3 + (size_t)l * FFF * DD;
            bias3[l] = p4 + (size_t)l * NQKV;
        }
    }

    // ---- side stream for weight conversion + layer-1 Q-tail GEMM -------------
    static cudaStream_t s2 = nullptr;
    static cudaEvent_t evF, evQ[2], evO[2], ev1[2], ev2[2], evA, evQd;
    if (!s2) {
        cudaStreamCreateWithFlags(&s2, cudaStreamNonBlocking);
        cudaEventCreateWithFlags(&evF, cudaEventDisableTiming);
        cudaEventCreateWithFlags(&evA, cudaEventDisableTiming);
        cudaEventCreateWithFlags(&evQd, cudaEventDisableTiming);
        for (int l = 0; l < 2; l++) {
            cudaEventCreateWithFlags(&evQ[l], cudaEventDisableTiming);
            cudaEventCreateWithFlags(&evO[l], cudaEventDisableTiming);
            cudaEventCreateWithFlags(&ev1[l], cudaEventDisableTiming);
            cudaEventCreateWithFlags(&ev2[l], cudaEventDisableTiming);
        }
    }

    cudaEventRecord(evF, 0);
    cudaStreamWaitEvent(s2, evF, 0);
    for (int l = 0; l < 2; l++) {
        long long wofs = (long long)l * DD * DD;
        conv_wt<<<dim3(DD/32, DD/32), 256, 0, s2>>>(Wq + wofs, wqkv[l],            DD, DD);
        conv_wt<<<dim3(DD/32, DD/32), 256, 0, s2>>>(Wk + wofs, wqkv[l] + DD*DD,    DD, DD);
        conv_wt<<<dim3(DD/32, DD/32), 256, 0, s2>>>(Wv + wofs, wqkv[l] + 2*DD*DD,  DD, DD);
        concat3<<<3, 256, 0, s2>>>(bq + l*DD, bk + l*DD, bv + l*DD, bias3[l]);
        cudaEventRecord(evQ[l], s2);
        conv_wt<<<dim3(DD/32, DD/32), 256, 0, s2>>>(Wo + wofs, wo[l], DD, DD);
        cudaEventRecord(evO[l], s2);
        conv_wt<<<dim3(FFF/32, DD/32), 256, 0, s2>>>(W1 + (long long)l*DD*FFF, w1[l], DD, FFF);
        cudaEventRecord(ev1[l], s2);
        conv_wt<<<dim3(DD/32, FFF/32), 256, 0, s2>>>(W2 + (long long)l*FFF*DD, w2[l], FFF, DD);
        cudaEventRecord(ev2[l], s2);
    }

    embed_ln_split<<<SS, 256>>>(input_ids, word_emb, pos_emb, eln_w, eln_b, h, ah);

    // =========================== layer 0 (full) ===========================
    {
        int l = 0;
        cudaStreamWaitEvent(0, evQ[l], 0);
        gemm_mma<3><<<dim3(NQKV/128, SS/128, 1), 256, GEMM_SMEM>>>(
            ah, wqkv[l], bias3[l], nullptr, 0, bh, SS, NQKV, DD, NQKV, 5);

        attn_mma_kernel<<<dim3(HH, 78), 128, ATTN_SMEM>>>(
            bh, rand_attn + l*HH*NBB*RRR, ah, pO, pm, pl, 0);
        attn_combine<<<dim3(24, 64), 64>>>(pO, pm, pl, ah, 1, 0);

        // Wo split-K=4
        cudaStreamWaitEvent(0, evO[l], 0);
        gemm_mma<3><<<dim3(DD/128, SS/128, 4), 256, GEMM_SMEM>>>(
            ah, wo[l], bo + l*DD, ap, PSZ, nullptr, SS, DD, DD, DD, 0);
        add_lnN<<<SS, 256>>>(h, ap, PSZ, 4, ln1_w + l*DD, ln1_b + l*DD, ah);

        cudaStreamWaitEvent(0, ev1[l], 0);
        gemm_mma<3><<<dim3(FFF/128, SS/128, 1), 256, GEMM_SMEM>>>(
            ah, w1[l], b1 + l*FFF, nullptr, 0, bh, SS, FFF, DD, FFF, 4);

        // W2 split-K=4
        cudaStreamWaitEvent(0, ev2[l], 0);
        gemm_mma<3><<<dim3(DD/128, SS/128, 4), 256, GEMM_SMEM>>>(
            bh, w2[l], b2 + l*DD, ap, PSZ, nullptr, SS, DD, FFF, DD, 0);
        add_lnN<<<SS, 256>>>(h, ap, PSZ, 4, ln2_w + l*DD, ln2_b + l*DD, ah);
    }

    // ================= layer 1 (pruned: only last row matters) =============
    {
        int l = 1;
        const size_t ro768  = (size_t)ROW0 * DD;
        const size_t ro3072 = (size_t)ROW0 * FFF;
        const size_t roqkv  = (size_t)ROW0 * NQKV;

        cudaEventRecord(evA, 0);

        // Q projection for last 128 rows only (side stream)
        cudaStreamWaitEvent(s2, evA, 0);
        gemm_mma<3><<<dim3(DD/128, 1, 1), 256, GEMM_SMEM, s2>>>(
            ah + ro768, wqkv[l], bias3[l], nullptr, 0, bh + roqkv,
            MTAIL, DD, DD, NQKV, 5);
        cudaEventRecord(evQd, s2);

        // K,V projection for all rows
        cudaStreamWaitEvent(0, evQ[l], 0);
        gemm_mma<3><<<dim3((2*DD)/128, SS/128, 1), 256, GEMM_SMEM>>>(
            ah, wqkv[l] + (size_t)DD * DD, bias3[l] + DD, nullptr, 0, bh + DD,
            SS, 2*DD, DD, NQKV, 5);

        // attention: only edge e=1 (q-block 63) chunks
        cudaStreamWaitEvent(0, evQd, 0);
        attn_mma_kernel<<<dim3(HH, 8), 128, ATTN_SMEM>>>(
            bh, rand_attn + l*HH*NBB*RRR, ah, pO, pm, pl, 70);
        attn_combine<<<dim3(12, 64), 64>>>(pO, pm, pl, ah, 2, 1);

        // Wo: last 128 rows only (split-K=2)
        cudaStreamWaitEvent(0, evO[l], 0);
        gemm_mma<3><<<dim3(DD/128, 1, 2), 256, GEMM_SMEM>>>(
            ah + ro768, wo[l], bo + l*DD, ap + ro768, PSZ, nullptr,
            MTAIL, DD, DD, DD, 0);
        add_lnN<<<MTAIL, 256>>>(h + ro768, ap + ro768, PSZ, 2,
                                ln1_w + l*DD, ln1_b + l*DD, ah + ro768);

        // FFN: last 128 rows only
        cudaStreamWaitEvent(0, ev1[l], 0);
        gemm_mma<3><<<dim3(FFF/128, 1, 1), 256, GEMM_SMEM>>>(
            ah + ro768, w1[l], b1 + l*FFF, nullptr, 0, bh + ro3072,
            MTAIL, FFF, DD, FFF, 4);
        cudaStreamWaitEvent(0, ev2[l], 0);
        gemm_mma<3><<<dim3(DD/128, 1, 2), 256, GEMM_SMEM>>>(
            bh + ro3072, w2[l], b2 + l*DD, ap + ro768, PSZ, nullptr,
            MTAIL, DD, FFF, DD, 0);
        add_lnN<<<MTAIL, 256>>>(h + ro768, ap + ro768, PSZ, 2,
                                ln2_w + l*DD, ln2_b + l*DD, ah + ro768);
    }

    classifier_kernel<<<1, 256>>>(h, Wc, bc, out);
}

// round 17
// speedup vs baseline: 1.0794x; 1.0794x over previous
#include <cuda_runtime.h>
#include <cuda_fp16.h>
#include <math.h>
#include <stdint.h>

#define SS 4096
#define DD 768
#define HH 12
#define DHH 64
#define NBB 64
#define BSS 64
#define RRR 3
#define FFF 3072
#define CCC 8
#define NQKV 2304
#define MTAIL 128
#define ROW0 (SS - MTAIL)
#define PSZ ((size_t)SS * DD)      // partial-buffer stride

// ---------------- scratch (device globals; no allocation allowed) -----------
__device__ __align__(16) float g_h  [SS*DD];
__device__ __align__(16) float g_ap [2*SS*DD];  // split-K partials (2)
__device__ __align__(16) __half g_ah[SS*FFF];   // activation hi
__device__ __align__(16) __half g_bh[SS*FFF];   // qkv hi / ffn-hidden hi
// per-layer fp16 weights (hi only)
__device__ __align__(16) __half g_wqkv[2][3*DD*DD];
__device__ __align__(16) __half g_wo  [2][DD*DD];
__device__ __align__(16) __half g_w1  [2][DD*FFF];
__device__ __align__(16) __half g_w2  [2][FFF*DD];
__device__ __align__(16) float  g_bias3[2][NQKV];
// edge-attention partials: 24 (h,e) x 8 chunks x 64 q x 64 d
__device__ __align__(16) float g_pO[24*8*64*64];
__device__ __align__(16) float g_pm[24*8*64];
__device__ __align__(16) float g_pl[24*8*64];

// ---------------- PTX helpers ------------------------------------------------
__device__ __forceinline__ uint32_t smem_addr(const void* p) {
    uint32_t a;
    asm("{ .reg .u64 t; cvta.to.shared.u64 t, %1; cvt.u32.u64 %0, t; }" : "=r"(a) : "l"(p));
    return a;
}
__device__ __forceinline__ void ldsm_x4(uint32_t addr, uint32_t* r) {
    asm volatile("ldmatrix.sync.aligned.m8n8.x4.shared.b16 {%0,%1,%2,%3}, [%4];"
        : "=r"(r[0]), "=r"(r[1]), "=r"(r[2]), "=r"(r[3]) : "r"(addr));
}
__device__ __forceinline__ void ldsm_x4_t(uint32_t addr, uint32_t* r) {
    asm volatile("ldmatrix.sync.aligned.m8n8.x4.trans.shared.b16 {%0,%1,%2,%3}, [%4];"
        : "=r"(r[0]), "=r"(r[1]), "=r"(r[2]), "=r"(r[3]) : "r"(addr));
}
__device__ __forceinline__ void mma_f16(float* c, const uint32_t* a, const uint32_t* b) {
    asm volatile("mma.sync.aligned.m16n8k16.row.col.f32.f16.f16.f32 "
        "{%0,%1,%2,%3}, {%4,%5,%6,%7}, {%8,%9}, {%0,%1,%2,%3};"
        : "+f"(c[0]), "+f"(c[1]), "+f"(c[2]), "+f"(c[3])
        : "r"(a[0]), "r"(a[1]), "r"(a[2]), "r"(a[3]), "r"(b[0]), "r"(b[1]));
}
__device__ __forceinline__ void mma4(float* c, const uint32_t* a, uint32_t b0, uint32_t b1) {
    uint32_t b[2] = {b0, b1};
    mma_f16(c, a, b);
}
#define CP_ASYNC(dst, src) asm volatile("cp.async.cg.shared.global [%0], [%1], 16;" :: "r"(dst), "l"(src))
#define CP_COMMIT()        asm volatile("cp.async.commit_group;")
#define CP_WAIT(n)         asm volatile("cp.async.wait_group %0;" :: "n"(n))

__device__ __forceinline__ uint32_t pack_h2(__half a, __half b) {
    __half2 t; t.x = a; t.y = b;
    return *(uint32_t*)&t;
}
__device__ __forceinline__ float tanh_fast(float x) {
    float y;
    asm("tanh.approx.f32 %0, %1;" : "=f"(y) : "f"(x));
    return y;
}

// ---------------- fp16 1-pass GEMM via mma.sync -------------------------------
// C = Ah * Bh^T + bias (fp32 accum). 2 tiles/stage, NS-stage cp.async pipeline.
// Split-K via blockIdx.z: partial z writes C + z*psz; bias only on z=0.
// ldo: output row stride. modes: 0 fp32 out, 4 gelu + fp16 hi, 5 fp16 hi
#define GEMM_SMEM 98304

template<int NS>
__global__ void __launch_bounds__(256, 2)
gemm_mma(const __half* __restrict__ Ah, const __half* __restrict__ Bh,
         const float* __restrict__ bias, float* __restrict__ C, size_t psz,
         __half* __restrict__ Oh,
         int M, int N, int K, int ldo, int mode)
{
    constexpr int STAGE = 2 * 16384;
    extern __shared__ __align__(128) char smem[];
    uint32_t sb = smem_addr(smem);
    int tid = threadIdx.x, lane = tid & 31, wid = tid >> 5;
    int wm = wid & 1, wn = wid >> 1;
    int n0 = blockIdx.x * 128, m0 = blockIdx.y * 128;
    int kz = blockIdx.z, nz = gridDim.z;
    const int KT = (K >> 6) / nz;
    const int kbase = kz * KT;
    float* Cout = C + (size_t)kz * psz;
    float bsc = (kz == 0) ? 1.f : 0.f;

    const __half* srcA = Ah + (size_t)m0 * K;
    const __half* srcB = Bh + (size_t)n0 * K;

    float acc[4][4][4];
#pragma unroll
    for (int i = 0; i < 4; i++)
#pragma unroll
        for (int j = 0; j < 4; j++)
#pragma unroll
            for (int u = 0; u < 4; u++) acc[i][j][u] = 0.f;

    auto load_stage = [&](int S, int ktIdx) {
        uint32_t sbase = sb + S * STAGE;
        int ko = (kbase + ktIdx) * 64;
#pragma unroll
        for (int t = 0; t < 2; t++) {
            const __half* sp = t ? srcB : srcA;
#pragma unroll
            for (int i = 0; i < 4; i++) {
                int id = tid + i * 256;
                int row = id >> 3, c = id & 7;
                const __half* src = sp + (size_t)row * K + ko + c * 8;
                uint32_t dst = sbase + t * 16384 + row * 128 + ((c ^ (row & 7)) << 4);
                CP_ASYNC(dst, src);
            }
        }
        CP_COMMIT();
    };

#pragma unroll
    for (int s = 0; s < NS - 1; s++)
        if (s < KT) load_stage(s, s);

    for (int kt = 0; kt < KT; kt++) {
        if (kt + NS - 1 < KT) { load_stage((kt + NS - 1) % NS, kt + NS - 1); CP_WAIT(NS - 1); }
        else                  { CP_WAIT(0); }
        __syncthreads();
        uint32_t st = sb + (kt % NS) * STAGE;
#pragma unroll
        for (int ks = 0; ks < 4; ks++) {
            uint32_t ahf[4][4], bhf[2][4];
#pragma unroll
            for (int mt = 0; mt < 4; mt++) {
                int row = wm * 64 + mt * 16 + (lane & 15);
                int kc = ks * 2 + (lane >> 4);
                uint32_t off = row * 128 + ((kc ^ (row & 7)) << 4);
                ldsm_x4(st + off, ahf[mt]);
            }
#pragma unroll
            for (int np = 0; np < 2; np++) {
                int row = wn * 32 + np * 16 + ((lane & 7) | ((lane & 16) >> 1));
                int kc = ks * 2 + ((lane >> 3) & 1);
                uint32_t off = row * 128 + ((kc ^ (row & 7)) << 4);
                ldsm_x4(st + 16384 + off, bhf[np]);
            }
#pragma unroll
            for (int mt = 0; mt < 4; mt++)
#pragma unroll
                for (int nt = 0; nt < 4; nt++)
                    mma_f16(acc[mt][nt], ahf[mt], &bhf[nt >> 1][(nt & 1) * 2]);
        }
        __syncthreads();
    }

#pragma unroll
    for (int mt = 0; mt < 4; mt++) {
        int mbase = m0 + wm * 64 + mt * 16 + (lane >> 2);
#pragma unroll
        for (int nt = 0; nt < 4; nt++) {
            int n = n0 + wn * 32 + nt * 8 + (lane & 3) * 2;
            float b0 = bias[n] * bsc, b1 = bias[n + 1] * bsc;
#pragma unroll
            for (int half = 0; half < 2; half++) {
                int m = mbase + half * 8;
                float v0 = acc[mt][nt][half * 2 + 0] + b0;
                float v1 = acc[mt][nt][half * 2 + 1] + b1;
                if (mode == 4) {
                    float u0 = 0.7978845608028654f * (v0 + 0.044715f * v0 * v0 * v0);
                    v0 = 0.5f * v0 * (1.f + tanh_fast(u0));
                    float u1 = 0.7978845608028654f * (v1 + 0.044715f * v1 * v1 * v1);
                    v1 = 0.5f * v1 * (1.f + tanh_fast(u1));
                }
                if (mode >= 4) {
                    *(uint32_t*)(Oh + (size_t)m * ldo + n) = pack_h2(__float2half_rn(v0), __float2half_rn(v1));
                } else {
                    float2 o; o.x = v0; o.y = v1;
                    *(float2*)(Cout + (size_t)m * ldo + n) = o;
                }
            }
        }
    }
}

// ---------------- W[K,N] fp32 -> Wt[N,K] fp16 hi ------------------------------
__global__ __launch_bounds__(256) void conv_wt(const float* __restrict__ W,
    __half* __restrict__ th, int K, int N)
{
    __shared__ float tile[32][33];
    int k0 = blockIdx.y * 32, n0 = blockIdx.x * 32;
    int tx = threadIdx.x & 31, ty = threadIdx.x >> 5;
#pragma unroll
    for (int r = ty; r < 32; r += 8)
        tile[r][tx] = W[(size_t)(k0 + r) * N + n0 + tx];
    __syncthreads();
#pragma unroll
    for (int r = ty; r < 32; r += 8) {
        float v = tile[tx][r];
        th[(size_t)(n0 + r) * K + k0 + tx] = __float2half_rn(v);
    }
}

__global__ __launch_bounds__(256) void concat3(const float* __restrict__ a,
    const float* __restrict__ b, const float* __restrict__ c, float* __restrict__ o)
{
    int i = blockIdx.x * 256 + threadIdx.x;
    if (i < DD) { o[i] = a[i]; o[DD + i] = b[i]; o[2 * DD + i] = c[i]; }
}

// ---------------- reductions -------------------------------------------------
__device__ __forceinline__ void block_reduce2(float &s1v, float &s2v) {
    __shared__ float sa[8], sb2[8];
    int lane = threadIdx.x & 31, w = threadIdx.x >> 5;
#pragma unroll
    for (int off = 16; off; off >>= 1) {
        s1v += __shfl_xor_sync(0xffffffffu, s1v, off);
        s2v += __shfl_xor_sync(0xffffffffu, s2v, off);
    }
    if (lane == 0) { sa[w] = s1v; sb2[w] = s2v; }
    __syncthreads();
    if (w == 0) {
        s1v = (lane < 8) ? sa[lane] : 0.f;
        s2v = (lane < 8) ? sb2[lane] : 0.f;
#pragma unroll
        for (int off = 4; off; off >>= 1) {
            s1v += __shfl_xor_sync(0xffffffffu, s1v, off);
            s2v += __shfl_xor_sync(0xffffffffu, s2v, off);
        }
        if (lane == 0) { sa[0] = s1v; sb2[0] = s2v; }
    }
    __syncthreads();
    s1v = sa[0]; s2v = sb2[0];
}

// ---------------- embedding + LN (hi out) -------------------------------------
__global__ __launch_bounds__(256) void embed_ln_split(
    const int* __restrict__ ids, const float* __restrict__ we,
    const float* __restrict__ pe, const float* __restrict__ w,
    const float* __restrict__ b, float* __restrict__ out,
    __half* __restrict__ oh)
{
    int row = blockIdx.x;
    int id = ids[row];
    float x[3], sum = 0.f, sq = 0.f;
#pragma unroll
    for (int r = 0; r < 3; r++) {
        int i = threadIdx.x + r * 256;
        x[r] = we[(long long)id * DD + i] + pe[row * DD + i];
        sum += x[r]; sq += x[r] * x[r];
    }
    block_reduce2(sum, sq);
    float mean = sum * (1.f / DD);
    float var  = sq * (1.f / DD) - mean * mean;
    float inv  = rsqrtf(var + 1e-12f);
#pragma unroll
    for (int r = 0; r < 3; r++) {
        int i = threadIdx.x + r * 256;
        float y = (x[r] - mean) * inv * w[i] + b[i];
        out[row * DD + i] = y;
        oh[row * DD + i] = __float2half_rn(y);
    }
}

// -------- residual (h + NZ split-K partials) + LN (hi out), NZ compile-time ----
template<int NZ>
__global__ void __launch_bounds__(256)
add_lnN(float* __restrict__ h, const float* __restrict__ ap, size_t psz,
        const float* __restrict__ w, const float* __restrict__ b,
        __half* __restrict__ oh)
{
    int row = blockIdx.x;
    float x[3], sum = 0.f, sq = 0.f;
#pragma unroll
    for (int r = 0; r < 3; r++) {
        int i = threadIdx.x + r * 256;
        float v = h[row * DD + i];
#pragma unroll
        for (int z = 0; z < NZ; z++)
            v += ap[(size_t)z * psz + row * DD + i];
        x[r] = v;
        sum += v; sq += v * v;
    }
    block_reduce2(sum, sq);
    float mean = sum * (1.f / DD);
    float var  = sq * (1.f / DD) - mean * mean;
    float inv  = rsqrtf(var + 1e-12f);
#pragma unroll
    for (int r = 0; r < 3; r++) {
        int i = threadIdx.x + r * 256;
        float y = (x[r] - mean) * inv * w[i] + b[i];
        h[row * DD + i] = y;
        oh[row * DD + i] = __float2half_rn(y);
    }
}

// ---------------- MMA flash attention (fp16, 1-pass) ---------------------------
#define AS_Q 0
#define AS_KV 8192
#define KV_STAGE 16384
#define ATTN_SMEM (8192 + 2 * KV_STAGE)

__global__ void __launch_bounds__(128)
attn_mma_kernel(const __half* __restrict__ sh, const int* __restrict__ rnd,
                __half* __restrict__ th,
                float* __restrict__ pO, float* __restrict__ pm, float* __restrict__ pl,
                int ybase)
{
    extern __shared__ __align__(128) char smem[];
    uint32_t sb = smem_addr(smem);
    int h = blockIdx.x, y = blockIdx.y + ybase;
    int tid = threadIdx.x, lane = tid & 31, w = tid >> 5;

    int qb, e = 0, z = 0;
    bool edge;
    if (y < 62) { qb = y + 1; edge = false; }
    else        { int t = y - 62; e = t >> 3; z = t & 7; qb = e ? (NBB - 1) : 0; edge = true; }

    int blks[8];
    if (edge) {
#pragma unroll
        for (int i = 0; i < 8; i++) blks[i] = z * 8 + i;
    } else {
        blks[0] = 0; blks[1] = NBB - 1; blks[2] = qb - 1; blks[3] = qb; blks[4] = qb + 1;
        const int* rp = rnd + (h * NBB + qb) * RRR;
        blks[5] = rp[0]; blks[6] = rp[1]; blks[7] = rp[2];
    }

    // ---- Q tile (hi) ----
    {
        int colq = h * DHH;
#pragma unroll
        for (int i = 0; i < 4; i++) {
            int idx = tid + i * 128;
            int row = idx >> 3, cu = idx & 7;
            const __half* src = sh + (size_t)(qb * BSS + row) * NQKV + colq + cu * 8;
            uint32_t dst = sb + AS_Q + row * 128 + ((cu ^ (row & 7)) << 4);
            CP_ASYNC(dst, src);
        }
    }
#define LOAD_KV(STG, KB) do {                                                   \
    uint32_t base_ = sb + AS_KV + (STG) * KV_STAGE;                             \
    _Pragma("unroll")                                                           \
    for (int i_ = 0; i_ < 8; i_++) {                                            \
        int idx_ = tid + i_ * 128;                                              \
        int t_ = idx_ >> 9, rem_ = idx_ & 511;                                  \
        int row_ = rem_ >> 3, cu_ = rem_ & 7;                                   \
        int col_ = (t_ + 1) * DD + h * DHH + cu_ * 8;                           \
        const __half* src_ = sh + (size_t)((KB) * BSS + row_) * NQKV + col_;    \
        uint32_t dst_ = base_ + t_ * 8192 + row_ * 128 + ((cu_ ^ (row_ & 7)) << 4); \
        CP_ASYNC(dst_, src_);                                                   \
    }                                                                           \
} while (0)

    LOAD_KV(0, blks[0]);
    CP_COMMIT();
    CP_WAIT(0);
    __syncthreads();

    uint32_t qfh[4][4];
#pragma unroll
    for (int ds = 0; ds < 4; ds++) {
        int row = w * 16 + (lane & 15);
        int cu = ds * 2 + (lane >> 4);
        uint32_t off = row * 128 + ((cu ^ (row & 7)) << 4);
        ldsm_x4(sb + AS_Q + off, qfh[ds]);
    }

    float o[8][4];
    float m[2] = {-1e30f, -1e30f}, l[2] = {0.f, 0.f};
#pragma unroll
    for (int j = 0; j < 8; j++)
#pragma unroll
        for (int u = 0; u < 4; u++) o[j][u] = 0.f;

    const float sc = 0.125f;

    for (int b = 0; b < 8; b++) {
        if (b + 1 < 8) { LOAD_KV((b + 1) & 1, blks[b + 1]); CP_COMMIT(); }
        uint32_t st = sb + AS_KV + (b & 1) * KV_STAGE;

        float s[8][4];
#pragma unroll
        for (int j = 0; j < 8; j++)
#pragma unroll
            for (int u = 0; u < 4; u++) s[j][u] = 0.f;
#pragma unroll
        for (int kb = 0; kb < 4; kb++) {
#pragma unroll
            for (int ds = 0; ds < 4; ds++) {
                int row = kb * 16 + (lane & 15);
                int cu = ds * 2 + (lane >> 4);
                uint32_t off = st + row * 128 + ((cu ^ (row & 7)) << 4);
                uint32_t kh4[4];
                ldsm_x4(off, kh4);
                mma4(s[2 * kb],     qfh[ds], kh4[0], kh4[2]);
                mma4(s[2 * kb + 1], qfh[ds], kh4[1], kh4[3]);
            }
        }

#pragma unroll
        for (int hf = 0; hf < 2; hf++) {
            float rm = -1e30f;
#pragma unroll
            for (int j = 0; j < 8; j++)
                rm = fmaxf(rm, fmaxf(s[j][hf * 2], s[j][hf * 2 + 1]));
            rm *= sc;
            rm = fmaxf(rm, __shfl_xor_sync(0xffffffffu, rm, 1));
            rm = fmaxf(rm, __shfl_xor_sync(0xffffffffu, rm, 2));
            float mn = fmaxf(m[hf], rm);
            float corr = __expf(m[hf] - mn);
            m[hf] = mn;
            float rs = 0.f;
#pragma unroll
            for (int j = 0; j < 8; j++) {
                s[j][hf * 2]     = __expf(s[j][hf * 2]     * sc - mn);
                s[j][hf * 2 + 1] = __expf(s[j][hf * 2 + 1] * sc - mn);
                rs += s[j][hf * 2] + s[j][hf * 2 + 1];
            }
            rs += __shfl_xor_sync(0xffffffffu, rs, 1);
            rs += __shfl_xor_sync(0xffffffffu, rs, 2);
            l[hf] = l[hf] * corr + rs;
#pragma unroll
            for (int j = 0; j < 8; j++) {
                o[j][hf * 2]     *= corr;
                o[j][hf * 2 + 1] *= corr;
            }
        }

#pragma unroll
        for (int ks = 0; ks < 4; ks++) {
            uint32_t ph4[4];
            ph4[0] = pack_h2(__float2half_rn(s[2 * ks][0]),     __float2half_rn(s[2 * ks][1]));
            ph4[1] = pack_h2(__float2half_rn(s[2 * ks][2]),     __float2half_rn(s[2 * ks][3]));
            ph4[2] = pack_h2(__float2half_rn(s[2 * ks + 1][0]), __float2half_rn(s[2 * ks + 1][1]));
            ph4[3] = pack_h2(__float2half_rn(s[2 * ks + 1][2]), __float2half_rn(s[2 * ks + 1][3]));
#pragma unroll
            for (int dc = 0; dc < 4; dc++) {
                int row = ks * 16 + (lane & 15);
                int cu = dc * 2 + (lane >> 4);
                uint32_t off = st + 8192 + row * 128 + ((cu ^ (row & 7)) << 4);
                uint32_t vh4[4];
                ldsm_x4_t(off, vh4);
                mma4(o[2 * dc],     ph4, vh4[0], vh4[1]);
                mma4(o[2 * dc + 1], ph4, vh4[2], vh4[3]);
            }
        }

        if (b + 1 < 8) { CP_WAIT(0); __syncthreads(); }
    }

    int g = lane >> 2;
    if (!edge) {
#pragma unroll
        for (int hf = 0; hf < 2; hf++) {
            float inv = 1.f / l[hf];
            int row = qb * BSS + w * 16 + g + hf * 8;
#pragma unroll
            for (int j = 0; j < 8; j++) {
                int col = h * DHH + j * 8 + (lane & 3) * 2;
                *(uint32_t*)(th + (size_t)row * DD + col) =
                    pack_h2(__float2half_rn(o[j][hf * 2] * inv),
                            __float2half_rn(o[j][hf * 2 + 1] * inv));
            }
        }
    } else {
        int cb = (h * 2 + e) * 8 + z;
        float* po = pO + (size_t)cb * 64 * 64;
#pragma unroll
        for (int hf = 0; hf < 2; hf++) {
            int qr = w * 16 + g + hf * 8;
#pragma unroll
            for (int j = 0; j < 8; j++) {
                float2 val; val.x = o[j][hf * 2]; val.y = o[j][hf * 2 + 1];
                *(float2*)(po + qr * 64 + j * 8 + (lane & 3) * 2) = val;
            }
            if ((lane & 3) == 0) {
                pm[cb * 64 + qr] = m[hf];
                pl[cb * 64 + qr] = l[hf];
            }
        }
    }
}

// combine edge partials: grid (nhe, 64), 64 threads (d); he = x*hestep + heoff
__global__ void __launch_bounds__(64)
attn_combine(const float* __restrict__ pO, const float* __restrict__ pm,
             const float* __restrict__ pl, __half* __restrict__ th,
             int hestep, int heoff)
{
    int he = blockIdx.x * hestep + heoff, q = blockIdx.y, d = threadIdx.x;
    int h = he >> 1, e = he & 1;
    float mv[8], M = -1e30f;
#pragma unroll
    for (int z = 0; z < 8; z++) {
        mv[z] = pm[(he * 8 + z) * 64 + q];
        M = fmaxf(M, mv[z]);
    }
    float L = 0.f, O = 0.f;
#pragma unroll
    for (int z = 0; z < 8; z++) {
        float w = __expf(mv[z] - M);
        L += w * pl[(he * 8 + z) * 64 + q];
        O += w * pO[((size_t)(he * 8 + z) * 64 + q) * 64 + d];
    }
    float r = O / L;
    int row = (e ? (NBB - 1) : 0) * BSS + q;
    th[row * DD + h * DHH + d] = __float2half_rn(r);
}

// ---------------- classifier --------------------------------------------------
__global__ __launch_bounds__(256) void classifier_kernel(
    const float* __restrict__ h, const float* __restrict__ Wc,
    const float* __restrict__ bc, float* __restrict__ out)
{
    int warp = threadIdx.x >> 5, lane = threadIdx.x & 31;
    if (warp >= CCC) return;
    const float* hr = h + (long long)(SS - 1) * DD;
    float s = 0.f;
    for (int d = lane; d < DD; d += 32) s += hr[d] * Wc[d * CCC + warp];
#pragma unroll
    for (int off = 16; off; off >>= 1) s += __shfl_xor_sync(0xffffffffu, s, off);
    if (lane == 0) out[warp] = s + bc[warp];
}

// ---------------- launch ------------------------------------------------------
extern "C" void kernel_launch(void* const* d_in, const int* in_sizes, int n_in,
                              void* d_out, int out_size)
{
    (void)in_sizes; (void)n_in; (void)out_size;
    const int*   input_ids = (const int*)  d_in[0];
    const int*   rand_attn = (const int*)  d_in[1];
    const float* word_emb  = (const float*)d_in[2];
    const float* pos_emb   = (const float*)d_in[3];
    const float* eln_w     = (const float*)d_in[4];
    const float* eln_b     = (const float*)d_in[5];
    const float* Wq        = (const float*)d_in[6];
    const float* bq        = (const float*)d_in[7];
    const float* Wk        = (const float*)d_in[8];
    const float* bk        = (const float*)d_in[9];
    const float* Wv        = (const float*)d_in[10];
    const float* bv        = (const float*)d_in[11];
    const float* Wo        = (const float*)d_in[12];
    const float* bo        = (const float*)d_in[13];
    const float* ln1_w     = (const float*)d_in[14];
    const float* ln1_b     = (const float*)d_in[15];
    const float* W1        = (const float*)d_in[16];
    const float* b1        = (const float*)d_in[17];
    const float* W2        = (const float*)d_in[18];
    const float* b2        = (const float*)d_in[19];
    const float* ln2_w     = (const float*)d_in[20];
    const float* ln2_b     = (const float*)d_in[21];
    const float* Wc        = (const float*)d_in[22];
    const float* bc        = (const float*)d_in[23];
    float* out = (float*)d_out;

    cudaFuncSetAttribute(gemm_mma<3>, cudaFuncAttributeMaxDynamicSharedMemorySize, GEMM_SMEM);
    cudaFuncSetAttribute(attn_mma_kernel, cudaFuncAttributeMaxDynamicSharedMemorySize, ATTN_SMEM);

    float *h, *ap, *pO, *pm, *pl;
    __half *ah, *bh;
    __half *wqkv[2], *wo[2], *w1[2], *w2[2];
    float  *bias3[2];
    cudaGetSymbolAddress((void**)&h,  g_h);
    cudaGetSymbolAddress((void**)&ap, g_ap);
    cudaGetSymbolAddress((void**)&ah, g_ah);
    cudaGetSymbolAddress((void**)&bh, g_bh);
    cudaGetSymbolAddress((void**)&pO, g_pO);
    cudaGetSymbolAddress((void**)&pm, g_pm);
    cudaGetSymbolAddress((void**)&pl, g_pl);
    {
        __half *p0, *p1, *p2, *p3; float* p4;
        cudaGetSymbolAddress((void**)&p0, g_wqkv);
        cudaGetSymbolAddress((void**)&p1, g_wo);
        cudaGetSymbolAddress((void**)&p2, g_w1);
        cudaGetSymbolAddress((void**)&p3, g_w2);
        cudaGetSymbolAddress((void**)&p4, g_bias3);
        for (int l = 0; l < 2; l++) {
            wqkv[l] = p0 + (size_t)l * 3 * DD * DD;
            wo[l]   = p1 + (size_t)l * DD * DD;
            w1[l]   = p2 + (size_t)l * DD * FFF;
            w2[l]   = p3 + (size_t)l * FFF * DD;
            bias3[l] = p4 + (size_t)l * NQKV;
        }
    }

    // ---- side stream for weight conversion + layer-1 Q-tail GEMM -------------
    static cudaStream_t s2 = nullptr;
    static cudaEvent_t evF, evQ[2], evO[2], ev1[2], ev2[2], evA, evQd;
    if (!s2) {
        cudaStreamCreateWithFlags(&s2, cudaStreamNonBlocking);
        cudaEventCreateWithFlags(&evF, cudaEventDisableTiming);
        cudaEventCreateWithFlags(&evA, cudaEventDisableTiming);
        cudaEventCreateWithFlags(&evQd, cudaEventDisableTiming);
        for (int l = 0; l < 2; l++) {
            cudaEventCreateWithFlags(&evQ[l], cudaEventDisableTiming);
            cudaEventCreateWithFlags(&evO[l], cudaEventDisableTiming);
            cudaEventCreateWithFlags(&ev1[l], cudaEventDisableTiming);
            cudaEventCreateWithFlags(&ev2[l], cudaEventDisableTiming);
        }
    }

    cudaEventRecord(evF, 0);
    cudaStreamWaitEvent(s2, evF, 0);
    for (int l = 0; l < 2; l++) {
        long long wofs = (long long)l * DD * DD;
        conv_wt<<<dim3(DD/32, DD/32), 256, 0, s2>>>(Wq + wofs, wqkv[l],            DD, DD);
        conv_wt<<<dim3(DD/32, DD/32), 256, 0, s2>>>(Wk + wofs, wqkv[l] + DD*DD,    DD, DD);
        conv_wt<<<dim3(DD/32, DD/32), 256, 0, s2>>>(Wv + wofs, wqkv[l] + 2*DD*DD,  DD, DD);
        concat3<<<3, 256, 0, s2>>>(bq + l*DD, bk + l*DD, bv + l*DD, bias3[l]);
        cudaEventRecord(evQ[l], s2);
        conv_wt<<<dim3(DD/32, DD/32), 256, 0, s2>>>(Wo + wofs, wo[l], DD, DD);
        cudaEventRecord(evO[l], s2);
        conv_wt<<<dim3(FFF/32, DD/32), 256, 0, s2>>>(W1 + (long long)l*DD*FFF, w1[l], DD, FFF);
        cudaEventRecord(ev1[l], s2);
        conv_wt<<<dim3(DD/32, FFF/32), 256, 0, s2>>>(W2 + (long long)l*FFF*DD, w2[l], FFF, DD);
        cudaEventRecord(ev2[l], s2);
    }

    embed_ln_split<<<SS, 256>>>(input_ids, word_emb, pos_emb, eln_w, eln_b, h, ah);

    // =========================== layer 0 (full) ===========================
    {
        int l = 0;
        cudaStreamWaitEvent(0, evQ[l], 0);
        gemm_mma<3><<<dim3(NQKV/128, SS/128, 1), 256, GEMM_SMEM>>>(
            ah, wqkv[l], bias3[l], nullptr, 0, bh, SS, NQKV, DD, NQKV, 5);

        attn_mma_kernel<<<dim3(HH, 78), 128, ATTN_SMEM>>>(
            bh, rand_attn + l*HH*NBB*RRR, ah, pO, pm, pl, 0);
        attn_combine<<<dim3(24, 64), 64>>>(pO, pm, pl, ah, 1, 0);

        // Wo split-K=2
        cudaStreamWaitEvent(0, evO[l], 0);
        gemm_mma<3><<<dim3(DD/128, SS/128, 2), 256, GEMM_SMEM>>>(
            ah, wo[l], bo + l*DD, ap, PSZ, nullptr, SS, DD, DD, DD, 0);
        add_lnN<2><<<SS, 256>>>(h, ap, PSZ, ln1_w + l*DD, ln1_b + l*DD, ah);

        cudaStreamWaitEvent(0, ev1[l], 0);
        gemm_mma<3><<<dim3(FFF/128, SS/128, 1), 256, GEMM_SMEM>>>(
            ah, w1[l], b1 + l*FFF, nullptr, 0, bh, SS, FFF, DD, FFF, 4);

        // W2 split-K=2
        cudaStreamWaitEvent(0, ev2[l], 0);
        gemm_mma<3><<<dim3(DD/128, SS/128, 2), 256, GEMM_SMEM>>>(
            bh, w2[l], b2 + l*DD, ap, PSZ, nullptr, SS, DD, FFF, DD, 0);
        add_lnN<2><<<SS, 256>>>(h, ap, PSZ, ln2_w + l*DD, ln2_b + l*DD, ah);
    }

    // ================= layer 1 (pruned: only last row matters) =============
    {
        int l = 1;
        const size_t ro768  = (size_t)ROW0 * DD;
        const size_t ro3072 = (size_t)ROW0 * FFF;
        const size_t roqkv  = (size_t)ROW0 * NQKV;

        cudaEventRecord(evA, 0);

        // Q projection for last 128 rows only (side stream)
        cudaStreamWaitEvent(s2, evA, 0);
        gemm_mma<3><<<dim3(DD/128, 1, 1), 256, GEMM_SMEM, s2>>>(
            ah + ro768, wqkv[l], bias3[l], nullptr, 0, bh + roqkv,
            MTAIL, DD, DD, NQKV, 5);
        cudaEventRecord(evQd, s2);

        // K,V projection for all rows
        cudaStreamWaitEvent(0, evQ[l], 0);
        gemm_mma<3><<<dim3((2*DD)/128, SS/128, 1), 256, GEMM_SMEM>>>(
            ah, wqkv[l] + (size_t)DD * DD, bias3[l] + DD, nullptr, 0, bh + DD,
            SS, 2*DD, DD, NQKV, 5);

        // attention: only edge e=1 (q-block 63) chunks
        cudaStreamWaitEvent(0, evQd, 0);
        attn_mma_kernel<<<dim3(HH, 8), 128, ATTN_SMEM>>>(
            bh, rand_attn + l*HH*NBB*RRR, ah, pO, pm, pl, 70);
        attn_combine<<<dim3(12, 64), 64>>>(pO, pm, pl, ah, 2, 1);

        // Wo: last 128 rows only (split-K=2)
        cudaStreamWaitEvent(0, evO[l], 0);
        gemm_mma<3><<<dim3(DD/128, 1, 2), 256, GEMM_SMEM>>>(
            ah + ro768, wo[l], bo + l*DD, ap + ro768, PSZ, nullptr,
            MTAIL, DD, DD, DD, 0);
        add_lnN<2><<<MTAIL, 256>>>(h + ro768, ap + ro768, PSZ,
                                   ln1_w + l*DD, ln1_b + l*DD, ah + ro768);

        // FFN: last 128 rows only
        cudaStreamWaitEvent(0, ev1[l], 0);
        gemm_mma<3><<<dim3(FFF/128, 1, 1), 256, GEMM_SMEM>>>(
            ah + ro768, w1[l], b1 + l*FFF, nullptr, 0, bh + ro3072,
            MTAIL, FFF, DD, FFF, 4);
        cudaStreamWaitEvent(0, ev2[l], 0);
        gemm_mma<3><<<dim3(DD/128, 1, 2), 256, GEMM_SMEM>>>(
            bh + ro3072, w2[l], b2 + l*DD, ap + ro768, PSZ, nullptr,
            MTAIL, DD, FFF, DD, 0);
        add_lnN<2><<<MTAIL, 256>>>(h + ro768, ap + ro768, PSZ,
                                   ln2_w + l*DD, ln2_b + l*DD, ah + ro768);
    }

    classifier_kernel<<<1, 256>>>(h, Wc, bc, out);
}